// round 2
// baseline (speedup 1.0000x reference)
#include <cuda_runtime.h>

// Problem constants (DAVIS346 voxelization)
#define CW 346
#define CH 260
#define CC 16
#define NUM_VOX (2 * CC * CH * CW)   // 2,877,440 floats (divisible by 4)

__global__ void vox_zero_kernel(float4* __restrict__ out, int n4) {
    int i = blockIdx.x * blockDim.x + threadIdx.x;
    if (i < n4) out[i] = make_float4(0.f, 0.f, 0.f, 0.f);
}

__global__ void vox_scatter_kernel(const float4* __restrict__ ev,
                                   float* __restrict__ out, int n) {
    int i = blockIdx.x * blockDim.x + threadIdx.x;
    if (i >= n) return;
    float4 e = ev[i];                 // x, y, t, p
    float t = e.z;
    if (t > 0.0f && t <= 1.0f) {
        int ibin = (int)ceilf(t * (float)CC) - 1;   // matches jnp.ceil(t*C)-1 in fp32
        int p01  = (e.w > 0.0f) ? 1 : 0;            // {-1,1} -> {0,1}
        int idx  = (int)e.x + CW * (int)e.y + CW * CH * (ibin + CC * p01);
        out[idx] = 1.0f;              // non-accumulating scatter: plain store is safe
    }
}

extern "C" void kernel_launch(void* const* d_in, const int* in_sizes, int n_in,
                              void* d_out, int out_size) {
    const float4* ev = (const float4*)d_in[0];
    float* out = (float*)d_out;
    int n = in_sizes[0] / 4;          // events are [N,4] float32

    // 1) zero the output (harness poisons d_out)
    int n4 = NUM_VOX / 4;
    vox_zero_kernel<<<(n4 + 255) / 256, 256>>>((float4*)out, n4);

    // 2) scatter 1.0f per event
    vox_scatter_kernel<<<(n + 255) / 256, 256>>>(ev, out, n);
}

// round 3
// speedup vs baseline: 1.0010x; 1.0010x over previous
#include <cuda_runtime.h>

// Problem constants (DAVIS346 voxelization)
#define CW 346
#define CH 260
#define CC 16
#define NUM_VOX (2 * CC * CH * CW)   // 2,877,440 floats (divisible by 4)
#define EV_PER_THREAD 4
#define TPB 256

__global__ void vox_zero_kernel(float4* __restrict__ out, int n4) {
    int i = blockIdx.x * blockDim.x + threadIdx.x;
    if (i < n4) out[i] = make_float4(0.f, 0.f, 0.f, 0.f);
}

__global__ __launch_bounds__(TPB)
void vox_scatter_kernel(const float4* __restrict__ ev,
                        float* __restrict__ out, int n) {
    int base = blockIdx.x * (TPB * EV_PER_THREAD) + threadIdx.x;

    float4 e[EV_PER_THREAD];
    #pragma unroll
    for (int k = 0; k < EV_PER_THREAD; k++) {
        int i = base + k * TPB;
        if (i < n) {
            e[k] = __ldcs(&ev[i]);        // streaming read, evict-first
        } else {
            e[k] = make_float4(0.f, 0.f, -1.f, 0.f);  // t=-1 -> invalid
        }
    }

    int  idx[EV_PER_THREAD];
    bool val[EV_PER_THREAD];
    #pragma unroll
    for (int k = 0; k < EV_PER_THREAD; k++) {
        float t = e[k].z;
        val[k] = (t > 0.0f) && (t <= 1.0f);
        int ibin = (int)ceilf(t * (float)CC) - 1;        // ceil(t*C)-1
        int p01  = (e[k].w > 0.0f) ? 1 : 0;              // {-1,1} -> {0,1}
        idx[k]   = (int)e[k].x + CW * (int)e[k].y
                 + CW * CH * (ibin + CC * p01);
    }

    // PDL: loads above ran concurrently with the zero kernel; stores must wait
    // until the zero kernel has fully completed.
    cudaGridDependencySynchronize();

    #pragma unroll
    for (int k = 0; k < EV_PER_THREAD; k++)
        if (val[k]) out[idx[k]] = 1.0f;   // non-accumulating scatter, races benign
}

extern "C" void kernel_launch(void* const* d_in, const int* in_sizes, int n_in,
                              void* d_out, int out_size) {
    const float4* ev = (const float4*)d_in[0];
    float* out = (float*)d_out;
    int n = in_sizes[0] / 4;              // events are [N,4] float32

    // 1) zero the output (harness poisons d_out)
    int n4 = NUM_VOX / 4;
    vox_zero_kernel<<<(n4 + TPB - 1) / TPB, TPB>>>((float4*)out, n4);

    // 2) scatter, launched with programmatic dependent launch so its event
    //    loads overlap the zero kernel.
    int blocks = (n + TPB * EV_PER_THREAD - 1) / (TPB * EV_PER_THREAD);
    cudaLaunchConfig_t cfg = {};
    cfg.gridDim  = dim3(blocks, 1, 1);
    cfg.blockDim = dim3(TPB, 1, 1);
    cfg.dynamicSmemBytes = 0;
    cfg.stream = 0;
    cudaLaunchAttribute attr[1];
    attr[0].id = cudaLaunchAttributeProgrammaticStreamSerialization;
    attr[0].val.programmaticStreamSerializationAllowed = 1;
    cfg.attrs = attr;
    cfg.numAttrs = 1;
    cudaLaunchKernelEx(&cfg, vox_scatter_kernel, ev, out, n);
}